// round 1
// baseline (speedup 1.0000x reference)
#include <cuda_runtime.h>

#define BATCH 4
#define SEQ   2048
#define DIMS  1024
#define NHEAD 16
#define HDIM  64
#define MROWS (BATCH*SEQ)

// Scratch (static device allocations — allowed; no cudaMalloc anywhere)
__device__ float g_q[(size_t)BATCH*NHEAD*SEQ*HDIM];   // [b,h,s,d]
__device__ float g_k[(size_t)BATCH*NHEAD*SEQ*HDIM];
__device__ float g_v[(size_t)BATCH*NHEAD*SEQ*HDIM];
__device__ float g_ctx[(size_t)BATCH*SEQ*DIMS];       // [b,s,h*64+d]

// ---------------------------------------------------------------------------
// Projection GEMM: C = scale * (A[M,K] @ W[N,K]^T + bias[N])
// 128x128 block tile, BK=16, 256 threads, 8x8 per thread.
// OUT_SEL: 0->g_q, 1->g_k, 2->g_v (head-scattered [b,h,s,d]); 3->outp plain [M,N]
// A_SEL:   0->Ap param, 1->g_ctx
// ---------------------------------------------------------------------------
template<int OUT_SEL, int A_SEL>
__global__ __launch_bounds__(256, 2) void proj_kernel(
    const float* __restrict__ Ap, const float* __restrict__ W,
    const float* __restrict__ bias, float* __restrict__ outp, float scale)
{
    const float* __restrict__ A = (A_SEL == 1) ? (const float*)g_ctx : Ap;
    float* out;
    if      (OUT_SEL == 0) out = g_q;
    else if (OUT_SEL == 1) out = g_k;
    else if (OUT_SEL == 2) out = g_v;
    else                   out = outp;

    const int BK = 16, LDT = 132;   // pad 128->132 to reduce store conflicts
    __shared__ float As[16*132];
    __shared__ float Bs[16*132];

    const int tid = threadIdx.x;
    const int m0 = blockIdx.y * 128;
    const int n0 = blockIdx.x * 128;
    const int tx = tid & 15;
    const int ty = tid >> 4;
    const int lr = tid >> 2;          // 0..63
    const int lc = (tid & 3) << 2;    // 0,4,8,12

    float acc[8][8];
#pragma unroll
    for (int i = 0; i < 8; ++i)
#pragma unroll
        for (int j = 0; j < 8; ++j) acc[i][j] = 0.f;

    for (int k0 = 0; k0 < DIMS; k0 += BK) {
#pragma unroll
        for (int rr = 0; rr < 2; ++rr) {
            const int row = lr + rr * 64;
            float4 av = *(const float4*)&A[(size_t)(m0 + row) * DIMS + k0 + lc];
            As[(lc+0)*LDT + row] = av.x;
            As[(lc+1)*LDT + row] = av.y;
            As[(lc+2)*LDT + row] = av.z;
            As[(lc+3)*LDT + row] = av.w;
            float4 wv4 = *(const float4*)&W[(size_t)(n0 + row) * DIMS + k0 + lc];
            Bs[(lc+0)*LDT + row] = wv4.x;
            Bs[(lc+1)*LDT + row] = wv4.y;
            Bs[(lc+2)*LDT + row] = wv4.z;
            Bs[(lc+3)*LDT + row] = wv4.w;
        }
        __syncthreads();
#pragma unroll
        for (int kk = 0; kk < BK; ++kk) {
            float4 a0 = *(const float4*)&As[kk*LDT + ty*8];
            float4 a1 = *(const float4*)&As[kk*LDT + ty*8 + 4];
            float4 b0 = *(const float4*)&Bs[kk*LDT + tx*8];
            float4 b1 = *(const float4*)&Bs[kk*LDT + tx*8 + 4];
            float a[8] = {a0.x,a0.y,a0.z,a0.w,a1.x,a1.y,a1.z,a1.w};
            float b[8] = {b0.x,b0.y,b0.z,b0.w,b1.x,b1.y,b1.z,b1.w};
#pragma unroll
            for (int i = 0; i < 8; ++i)
#pragma unroll
                for (int j = 0; j < 8; ++j)
                    acc[i][j] = fmaf(a[i], b[j], acc[i][j]);
        }
        __syncthreads();
    }

#pragma unroll
    for (int i = 0; i < 8; ++i) {
        const int m = m0 + ty*8 + i;
#pragma unroll
        for (int jj = 0; jj < 2; ++jj) {
            const int n = n0 + tx*8 + jj*4;
            float4 bb = *(const float4*)&bias[n];
            float4 r;
            r.x = (acc[i][jj*4+0] + bb.x) * scale;
            r.y = (acc[i][jj*4+1] + bb.y) * scale;
            r.z = (acc[i][jj*4+2] + bb.z) * scale;
            r.w = (acc[i][jj*4+3] + bb.w) * scale;
            if (OUT_SEL < 3) {
                const int bb_ = m / SEQ, s = m % SEQ;
                const int h = n / HDIM, d = n % HDIM;
                *(float4*)&out[(((size_t)bb_*NHEAD + h)*SEQ + s)*HDIM + d] = r;
            } else {
                *(float4*)&out[(size_t)m*DIMS + n] = r;
            }
        }
    }
}

// ---------------------------------------------------------------------------
// Fused flash attention, fp32. One CTA = one (b,h) x 64 q-rows.
// 256 threads as 16x16; each thread owns a 4x4 patch of the 64x64 S tile and
// a 4(rows) x 4(hd) patch of the output accumulator.
// Q staged transposed [d][row]; K natural [s][d] pad 65 (scalar reads);
// V natural pad 68 (float4 reads); P [row][k] pad 68.
// ---------------------------------------------------------------------------
#define ATTN_LK 65
#define ATTN_LV 68
#define ATTN_LP 68
#define ATTN_SMEM_FLOATS (HDIM*64 + 64*ATTN_LK + 64*ATTN_LV + 64*ATTN_LP + 64)
#define ATTN_SMEM_BYTES  (ATTN_SMEM_FLOATS * 4)

__global__ __launch_bounds__(256) void attn_kernel(const int* __restrict__ mask)
{
    extern __shared__ float smbuf[];
    float* Qs = smbuf;                    // [64 d][64 row]
    float* Ks = Qs + HDIM*64;             // [64 s][65]
    float* Vs = Ks + 64*ATTN_LK;          // [64 s][68]
    float* Ps = Vs + 64*ATTN_LV;          // [64 row][68]
    int*   Ms = (int*)(Ps + 64*ATTN_LP);  // [64]

    const int bh = blockIdx.y;
    const int b  = bh >> 4;
    const int h  = bh & 15;
    const int q0 = blockIdx.x * 64;
    const float* __restrict__ Qg = g_q + (size_t)bh*SEQ*HDIM;
    const float* __restrict__ Kg = g_k + (size_t)bh*SEQ*HDIM;
    const float* __restrict__ Vg = g_v + (size_t)bh*SEQ*HDIM;

    const int tid = threadIdx.x;
    const int tx = tid & 15;   // S-tile col group / hd col group
    const int ty = tid >> 4;   // q-row group

    // Load Q tile once, transposed into [d][row]
#pragma unroll
    for (int it = 0; it < 16; ++it) {
        int idx = tid + it*256;           // 0..4095
        int r = idx >> 6, d = idx & 63;
        Qs[d*64 + r] = Qg[(size_t)(q0 + r)*HDIM + d];
    }

    float m_i[4], l_i[4], acc[4][4];
#pragma unroll
    for (int i = 0; i < 4; ++i) {
        m_i[i] = -1e30f; l_i[i] = 0.f;
#pragma unroll
        for (int j = 0; j < 4; ++j) acc[i][j] = 0.f;
    }

    for (int k0 = 0; k0 < SEQ; k0 += 64) {
        __syncthreads();  // previous iter's Vs/Ps readers done
#pragma unroll
        for (int it = 0; it < 4; ++it) {
            int idx = tid + it*256;       // 1024 float4s
            int r = idx >> 4, c = (idx & 15) << 2;
            float4 kv = *(const float4*)&Kg[(size_t)(k0 + r)*HDIM + c];
            Ks[r*ATTN_LK + c + 0] = kv.x;
            Ks[r*ATTN_LK + c + 1] = kv.y;
            Ks[r*ATTN_LK + c + 2] = kv.z;
            Ks[r*ATTN_LK + c + 3] = kv.w;
            *(float4*)&Vs[r*ATTN_LV + c] = *(const float4*)&Vg[(size_t)(k0 + r)*HDIM + c];
        }
        if (tid < 64) Ms[tid] = mask[b*SEQ + k0 + tid];
        __syncthreads();

        // S = Q K^T (4x4 per thread over hd=64)
        float sf[4][4];
#pragma unroll
        for (int i = 0; i < 4; ++i)
#pragma unroll
            for (int j = 0; j < 4; ++j) sf[i][j] = 0.f;

#pragma unroll 8
        for (int kk = 0; kk < HDIM; ++kk) {
            float4 q = *(const float4*)&Qs[kk*64 + ty*4];
            float qa[4] = {q.x, q.y, q.z, q.w};
            float ka[4];
#pragma unroll
            for (int j = 0; j < 4; ++j)
                ka[j] = Ks[(tx*4 + j)*ATTN_LK + kk];
#pragma unroll
            for (int i = 0; i < 4; ++i)
#pragma unroll
                for (int j = 0; j < 4; ++j)
                    sf[i][j] = fmaf(qa[i], ka[j], sf[i][j]);
        }

        // mask (mask==0 -> -inf)
#pragma unroll
        for (int j = 0; j < 4; ++j) {
            if (Ms[tx*4 + j] == 0) {
#pragma unroll
                for (int i = 0; i < 4; ++i) sf[i][j] = -1e30f;
            }
        }

        // online softmax per row (reduce across the 16 tx lanes)
#pragma unroll
        for (int i = 0; i < 4; ++i) {
            float rm = fmaxf(fmaxf(sf[i][0], sf[i][1]), fmaxf(sf[i][2], sf[i][3]));
#pragma unroll
            for (int off = 1; off < 16; off <<= 1)
                rm = fmaxf(rm, __shfl_xor_sync(0xffffffffu, rm, off));
            const float mn = fmaxf(m_i[i], rm);
            const float corr = __expf(m_i[i] - mn);
            m_i[i] = mn;
            float rs = 0.f;
#pragma unroll
            for (int j = 0; j < 4; ++j) {
                sf[i][j] = __expf(sf[i][j] - mn);
                rs += sf[i][j];
            }
#pragma unroll
            for (int off = 1; off < 16; off <<= 1)
                rs += __shfl_xor_sync(0xffffffffu, rs, off);
            l_i[i] = l_i[i]*corr + rs;
#pragma unroll
            for (int j = 0; j < 4; ++j) acc[i][j] *= corr;
            *(float4*)&Ps[(ty*4 + i)*ATTN_LP + tx*4] =
                make_float4(sf[i][0], sf[i][1], sf[i][2], sf[i][3]);
        }
        __syncthreads();

        // acc += P @ V
#pragma unroll 8
        for (int kk = 0; kk < 64; ++kk) {
            float4 v = *(const float4*)&Vs[kk*ATTN_LV + tx*4];
#pragma unroll
            for (int i = 0; i < 4; ++i) {
                float p = Ps[(ty*4 + i)*ATTN_LP + kk];
                acc[i][0] = fmaf(p, v.x, acc[i][0]);
                acc[i][1] = fmaf(p, v.y, acc[i][1]);
                acc[i][2] = fmaf(p, v.z, acc[i][2]);
                acc[i][3] = fmaf(p, v.w, acc[i][3]);
            }
        }
    }

    // normalize and write ctx in [b,s, h*64+d] layout
#pragma unroll
    for (int i = 0; i < 4; ++i) {
        const int srow = q0 + ty*4 + i;
        const float inv = 1.f / l_i[i];
        float4 r = make_float4(acc[i][0]*inv, acc[i][1]*inv, acc[i][2]*inv, acc[i][3]*inv);
        *(float4*)&g_ctx[((size_t)b*SEQ + srow)*DIMS + h*HDIM + tx*4] = r;
    }
}

// ---------------------------------------------------------------------------
extern "C" void kernel_launch(void* const* d_in, const int* in_sizes, int n_in,
                              void* d_out, int out_size)
{
    const float* input = (const float*)d_in[0];
    const int*   mask  = (const int*)d_in[1];
    const float* wq = (const float*)d_in[2];
    const float* bq = (const float*)d_in[3];
    const float* wk = (const float*)d_in[4];
    const float* bk = (const float*)d_in[5];
    const float* wv = (const float*)d_in[6];
    const float* bv = (const float*)d_in[7];
    const float* wo = (const float*)d_in[8];
    const float* bo = (const float*)d_in[9];
    float* out = (float*)d_out;

    (void)in_sizes; (void)n_in; (void)out_size;

    dim3 pgrid(DIMS/128, MROWS/128);   // 8 x 64

    // Q scaled by 1/sqrt(64) (after bias, matching reference)
    proj_kernel<0,0><<<pgrid, 256>>>(input, wq, bq, nullptr, 0.125f);
    proj_kernel<1,0><<<pgrid, 256>>>(input, wk, bk, nullptr, 1.0f);
    proj_kernel<2,0><<<pgrid, 256>>>(input, wv, bv, nullptr, 1.0f);

    cudaFuncSetAttribute(attn_kernel,
                         cudaFuncAttributeMaxDynamicSharedMemorySize,
                         ATTN_SMEM_BYTES);
    attn_kernel<<<dim3(SEQ/64, BATCH*NHEAD), 256, ATTN_SMEM_BYTES>>>(mask);

    proj_kernel<3,1><<<pgrid, 256>>>(nullptr, wo, bo, out, 1.0f);
}